// round 14
// baseline (speedup 1.0000x reference)
#include <cuda_runtime.h>
#include <cuda_fp16.h>
#include <cstdint>

#define BATCH 4096
#define DDIM  1024
#define NDIM  16384
#define KSEL  32

// ---------------- scratch ----------------------------------------------------
__device__ __align__(256) unsigned short g_a0[BATCH * DDIM];
__device__ __align__(256) unsigned short g_a1[BATCH * DDIM];
__device__ __align__(256) unsigned short g_b0[NDIM * DDIM];
__device__ __align__(256) unsigned short g_b1[NDIM * DDIM];
__device__ float g_wdt[NDIM * DDIM];
__device__ int   g_idx[BATCH * KSEL];
__device__ float g_val[BATCH * KSEL];

// ---------------- helpers ------------------------------------------------------
__device__ __forceinline__ uint32_t smem_u32(const void* p) {
    uint32_t a;
    asm("{ .reg .u64 t; cvta.to.shared.u64 t, %1; cvt.u32.u64 %0, t; }" : "=r"(a) : "l"(p));
    return a;
}
__device__ __forceinline__ void cp_async16(uint32_t dst, const void* src) {
    asm volatile("cp.async.cg.shared.global [%0], [%1], 16;" :: "r"(dst), "l"(src));
}
#define LDSM_X4(R, addr) \
    asm volatile("ldmatrix.sync.aligned.m8n8.x4.shared.b16 {%0,%1,%2,%3}, [%4];" \
        : "=r"((R)[0]), "=r"((R)[1]), "=r"((R)[2]), "=r"((R)[3]) : "r"(addr))

__device__ __forceinline__ void mma16816(float* c, const uint32_t* a, const uint32_t* b) {
    asm volatile("mma.sync.aligned.m16n8k16.row.col.f32.f16.f16.f32 "
        "{%0,%1,%2,%3}, {%4,%5,%6,%7}, {%8,%9}, {%0,%1,%2,%3};"
        : "+f"(c[0]), "+f"(c[1]), "+f"(c[2]), "+f"(c[3])
        : "r"(a[0]), "r"(a[1]), "r"(a[2]), "r"(a[3]), "r"(b[0]), "r"(b[1]));
}

// ---------------- split conversion (fp16 2-term) ------------------------------
__device__ __forceinline__ void split2(float a, unsigned short& h0, unsigned short& h1) {
    __half b0 = __float2half_rn(a);
    float r = a - __half2float(b0);
    __half b1 = __float2half_rn(r);
    h0 = __half_as_ushort(b0);
    h1 = __half_as_ushort(b1);
}

// ---------------- fused prep: convA + convB + transpose -----------------------
__global__ __launch_bounds__(256) void prep_kernel(const float* __restrict__ x,
                                                   const float* __restrict__ bdec,
                                                   const float* __restrict__ wenc,
                                                   const float* __restrict__ wdec) {
    const int b = blockIdx.x;
    const int tid = threadIdx.x;
    if (b < 4096) {
        int i = b * 256 + tid;
        float4 xv = reinterpret_cast<const float4*>(x)[i];
        float4 bv = reinterpret_cast<const float4*>(bdec)[i & 255];
        float a[4] = {xv.x - bv.x, xv.y - bv.y, xv.z - bv.z, xv.w - bv.w};
        ushort4 o0, o1;
        split2(a[0], o0.x, o1.x); split2(a[1], o0.y, o1.y);
        split2(a[2], o0.z, o1.z); split2(a[3], o0.w, o1.w);
        reinterpret_cast<ushort4*>(g_a0)[i] = o0;
        reinterpret_cast<ushort4*>(g_a1)[i] = o1;
    } else if (b < 20480) {
        int i = (b - 4096) * 256 + tid;
        float4 xv = reinterpret_cast<const float4*>(wenc)[i];
        float a[4] = {xv.x, xv.y, xv.z, xv.w};
        ushort4 o0, o1;
        split2(a[0], o0.x, o1.x); split2(a[1], o0.y, o1.y);
        split2(a[2], o0.z, o1.z); split2(a[3], o0.w, o1.w);
        reinterpret_cast<ushort4*>(g_b0)[i] = o0;
        reinterpret_cast<ushort4*>(g_b1)[i] = o1;
    } else {
        __shared__ float tile[32][33];
        int idx = b - 20480;
        int bx = idx & 511;
        int by = idx >> 9;
        int tx = tid & 31, ty = tid >> 5;
        int n  = bx * 32 + tx;
        int d0 = by * 32;
#pragma unroll
        for (int i = ty; i < 32; i += 8)
            tile[i][tx] = wdec[(size_t)(d0 + i) * NDIM + n];
        __syncthreads();
        int d  = d0 + tx;
        int n0 = bx * 32;
#pragma unroll
        for (int i = ty; i < 32; i += 8)
            g_wdt[(size_t)(n0 + i) * DDIM + d] = tile[tx][i];
    }
}

// ---------------- mma.sync GEMM: h_pre = (x-b_dec) @ W_enc^T + b_enc ---------
// R7 inner loop (known-good: 872us, tensor 78.3%)
#define TILE_B   (128 * 64)
#define STAGE_B  (4 * TILE_B)
#define GEMM_SMEM (3 * STAGE_B)

__device__ __forceinline__ uint32_t swz(int r, int s) {
    return (uint32_t)(r * 64 + ((s ^ ((r >> 1) & 3)) << 4));
}

__global__ __launch_bounds__(256, 2) void gemm_mma_kernel(const float* __restrict__ benc,
                                                          float* __restrict__ hpre) {
    extern __shared__ unsigned char smem[];
    __shared__ float sbenc[128];
    const uint32_t sb = smem_u32(smem);
    const int tid  = threadIdx.x;
    const int wid  = tid >> 5;
    const int lane = tid & 31;

    const int bid  = blockIdx.x;
    const int band = bid >> 11;
    const int rr   = bid & 2047;
    const int nb   = rr >> 4;
    const int mb   = (band << 4) + (rr & 15);
    const int m0 = mb * 128, n0 = nb * 128;

    if (tid < 128) sbenc[tid] = benc[n0 + tid];

    const unsigned short* srcs[4] = {
        g_a0 + (size_t)m0 * DDIM, g_a1 + (size_t)m0 * DDIM,
        g_b0 + (size_t)n0 * DDIM, g_b1 + (size_t)n0 * DDIM };

    auto load_stage = [&](int kt) {
        const uint32_t base = sb + (uint32_t)(kt % 3) * STAGE_B;
#pragma unroll
        for (int t = 0; t < 4; t++) {
            const unsigned short* src = srcs[t] + kt * 32;
#pragma unroll
            for (int i = 0; i < 2; i++) {
                int id = tid + i * 256;
                int row = id >> 2, seg = id & 3;
                cp_async16(base + (uint32_t)t * TILE_B + swz(row, seg),
                           src + (size_t)row * DDIM + seg * 8);
            }
        }
        asm volatile("cp.async.commit_group;" ::: "memory");
    };

    float c[4][4][4];
#pragma unroll
    for (int i = 0; i < 4; i++)
#pragma unroll
        for (int j = 0; j < 4; j++)
#pragma unroll
            for (int q = 0; q < 4; q++) c[i][j][q] = 0.0f;

    const int wm = wid & 1;
    const int wn = wid >> 1;

    const int a_row = wm * 64 + (lane & 15);
    const int a_hi  = lane >> 4;
    const int b_row = wn * 32 + (lane & 7) + ((lane >> 4) << 3);
    const int b_hi  = (lane >> 3) & 1;

    load_stage(0);
    load_stage(1);

    for (int kt = 0; kt < 32; kt++) {
        if (kt < 31) asm volatile("cp.async.wait_group 1;" ::: "memory");
        else         asm volatile("cp.async.wait_group 0;" ::: "memory");
        __syncthreads();
        if (kt + 2 < 32) load_stage(kt + 2);

        const uint32_t base = sb + (uint32_t)(kt % 3) * STAGE_B;
        const uint32_t aB0 = base, aB1 = base + TILE_B;
        const uint32_t bB0 = base + 2 * TILE_B, bB1 = base + 3 * TILE_B;

#pragma unroll
        for (int kk = 0; kk < 2; kk++) {
            uint32_t b0f[4][2], b1f[4][2];
#pragma unroll
            for (int p = 0; p < 2; p++) {
                uint32_t off = swz(b_row + p * 16, kk * 2 + b_hi);
                uint32_t r4[4];
                LDSM_X4(r4, bB0 + off);
                b0f[2*p][0] = r4[0]; b0f[2*p][1] = r4[1];
                b0f[2*p+1][0] = r4[2]; b0f[2*p+1][1] = r4[3];
                LDSM_X4(r4, bB1 + off);
                b1f[2*p][0] = r4[0]; b1f[2*p][1] = r4[1];
                b1f[2*p+1][0] = r4[2]; b1f[2*p+1][1] = r4[3];
            }
#pragma unroll
            for (int mi = 0; mi < 4; mi++) {
                uint32_t a0f[4], a1f[4];
                uint32_t off = swz(a_row + mi * 16, kk * 2 + a_hi);
                LDSM_X4(a0f, aB0 + off);
                LDSM_X4(a1f, aB1 + off);
#pragma unroll
                for (int ni = 0; ni < 4; ni++) {
                    mma16816(c[mi][ni], a0f, b0f[ni]);
                    mma16816(c[mi][ni], a0f, b1f[ni]);
                    mma16816(c[mi][ni], a1f, b0f[ni]);
                }
            }
        }
    }
    __syncthreads();

    const int erow = m0 + wm * 64 + (lane >> 2);
    const int ecol0 = wn * 32 + (lane & 3) * 2;
#pragma unroll
    for (int mi = 0; mi < 4; mi++) {
#pragma unroll
        for (int ni = 0; ni < 4; ni++) {
            const int col = ecol0 + ni * 8;
            const float be0 = sbenc[col], be1 = sbenc[col + 1];
            float* p0 = hpre + (size_t)(erow + mi * 16) * NDIM + n0 + col;
            float* p1 = hpre + (size_t)(erow + mi * 16 + 8) * NDIM + n0 + col;
            float2 v0 = {c[mi][ni][0] + be0, c[mi][ni][1] + be1};
            float2 v1 = {c[mi][ni][2] + be0, c[mi][ni][3] + be1};
            __stcs(reinterpret_cast<float2*>(p0), v0);
            __stcs(reinterpret_cast<float2*>(p1), v1);
        }
    }
}

// ---------------- top-k: R13 logic, 1024 threads -------------------------------
#define CAND_MAX 2048
#define EQCAP    256
#define TOPK_SMEM ((NDIM + 256 + 32 + CAND_MAX + EQCAP) * 4)
#define TTHREADS 1024

// suffix sum over 256 bins held by threads 0..255 (warps 0..7).
// shm32: 32-word scratch (warp totals [0..7], exclusive tails [16..23]).
__device__ __forceinline__ void suffix_scan256_w16(unsigned val, volatile unsigned* shm32,
                                                   int tid, unsigned& ge, unsigned& gt) {
    const int lane = tid & 31;
    const int wid  = tid >> 5;
    unsigned v = val;
    if (wid < 8) {
#pragma unroll
        for (int off = 1; off < 32; off <<= 1) {
            unsigned t = __shfl_down_sync(0xFFFFFFFFu, v, off);
            if (lane + off < 32) v += t;
        }
        if (lane == 0) shm32[wid] = v;
    }
    __syncthreads();
    if (wid == 0) {
        unsigned w = (lane < 8) ? shm32[lane] : 0u;
        unsigned u = w;
#pragma unroll
        for (int off = 1; off < 8; off <<= 1) {
            unsigned t = __shfl_down_sync(0xFFFFFFFFu, u, off);
            if (lane + off < 8) u += t;
        }
        if (lane < 8) shm32[16 + lane] = u - w;   // exclusive tails
    }
    __syncthreads();
    if (wid < 8) {
        unsigned tx = shm32[16 + wid];
        v += tx;
        ge = v;
        unsigned nv = __shfl_down_sync(0xFFFFFFFFu, v, 1);
        gt = (lane < 31) ? nv : tx;
    } else {
        ge = 0; gt = 0;
    }
}

__device__ __forceinline__ unsigned key_xform(unsigned u) {
    return (u & 0x80000000u) ? ~u : (u | 0x80000000u);
}
__device__ __forceinline__ float val_of(unsigned u) {
    return __uint_as_float((u >> 31) ? (u ^ 0x80000000u) : ~u);
}

__global__ __launch_bounds__(TTHREADS, 2) void topk_kernel(const float* __restrict__ hpre,
                                                           float* __restrict__ hsparse) {
    extern __shared__ unsigned sm[];
    unsigned* keys  = sm;                      // 16384
    unsigned* hist  = sm + NDIM;               // 256
    unsigned* shm32 = hist + 256;              // 32
    unsigned* ckey  = shm32 + 32;              // CAND_MAX
    unsigned* eqlst = ckey + CAND_MAX;         // EQCAP
    __shared__ unsigned s_b, s_kr, s_nc, s_ngt, s_neq;
    const int row = blockIdx.x;
    const int tid = threadIdx.x;
    const int lane = tid & 31;
    const float* in = hpre + (size_t)row * NDIM;
    const uint32_t keys_sm = smem_u32(keys);

    // stage whole row via cp.async (4 chunks per thread)
#pragma unroll
    for (int i = 0; i < 4; i++) {
        int c = tid + i * TTHREADS;            // 4096 16B-chunks
        cp_async16(keys_sm + (uint32_t)c * 16u, in + c * 4);
    }
    asm volatile("cp.async.commit_group;" ::: "memory");
    if (tid < 256) hist[tid] = 0;
    if (tid == 0) { s_nc = 0; s_ngt = 0; s_neq = 0; }
    asm volatile("cp.async.wait_group 0;" ::: "memory");
    __syncthreads();

    // sweep 1 (4 iters): transform in place + histogram top byte
    for (int i = tid; i < NDIM / 4; i += TTHREADS) {
        uint4 r = reinterpret_cast<uint4*>(keys)[i];
        unsigned u0 = key_xform(r.x), u1 = key_xform(r.y);
        unsigned u2 = key_xform(r.z), u3 = key_xform(r.w);
        uint4 o = {u0, u1, u2, u3};
        reinterpret_cast<uint4*>(keys)[i] = o;
        unsigned bins[4] = {u0 >> 24, u1 >> 24, u2 >> 24, u3 >> 24};
#pragma unroll
        for (int c = 0; c < 4; c++) {
            unsigned msk = __match_any_sync(0xFFFFFFFFu, bins[c]);
            if (lane == (__ffs(msk) - 1)) atomicAdd(&hist[bins[c]], __popc(msk));
        }
    }
    __syncthreads();
    {
        unsigned ge, gt;
        unsigned hv = (tid < 256) ? hist[tid] : 0u;
        suffix_scan256_w16(hv, shm32, tid, ge, gt);
        if (tid < 256 && gt < KSEL && KSEL <= ge) { s_b = (unsigned)tid; s_kr = KSEL - gt; }
    }
    __syncthreads();
    const unsigned topbyte = s_b;
    unsigned krem = s_kr;

    // sweep 2 (4 iters, uint4): ballot-aggregated compaction
    for (int i = tid; i < NDIM / 4; i += TTHREADS) {
        uint4 r = reinterpret_cast<uint4*>(keys)[i];
        unsigned us[4] = {r.x, r.y, r.z, r.w};
#pragma unroll
        for (int c = 0; c < 4; c++) {
            bool p = (us[c] >> 24) == topbyte;
            unsigned ball = __ballot_sync(0xFFFFFFFFu, p);
            unsigned base = 0;
            if (lane == 0 && ball) base = atomicAdd(&s_nc, (unsigned)__popc(ball));
            base = __shfl_sync(0xFFFFFFFFu, base, 0);
            if (p) {
                unsigned pos = base + __popc(ball & ((1u << lane) - 1u));
                if (pos < CAND_MAX) ckey[pos] = us[c];
            }
        }
    }
    __syncthreads();
    const bool overflow = (s_nc > (unsigned)CAND_MAX);
    const unsigned* csrc = overflow ? keys : ckey;
    const unsigned nc = overflow ? (unsigned)NDIM : s_nc;

    // passes 2-4 over candidates only
    unsigned prefix = topbyte << 24, pmask = 0xFF000000u;
    for (int shift = 16; shift >= 0; shift -= 8) {
        if (tid < 256) hist[tid] = 0;
        __syncthreads();
        for (unsigned j = tid; j < nc; j += TTHREADS) {
            unsigned u = csrc[j];
            if ((u & pmask) == prefix) atomicAdd(&hist[(u >> shift) & 255], 1u);
        }
        __syncthreads();
        unsigned ge, gt;
        unsigned hv = (tid < 256) ? hist[tid] : 0u;
        suffix_scan256_w16(hv, shm32, tid, ge, gt);
        if (tid < 256 && gt < krem && krem <= ge) { s_b = (unsigned)tid; s_kr = krem - gt; }
        __syncthreads();
        prefix |= (s_b << shift);
        pmask  |= (0xFFu << shift);
        krem = s_kr;
        __syncthreads();
    }
    const unsigned T = prefix;
    const unsigned needeq = krem;

    // sweep 3 (4 iters): write h_sparse (streaming) + collect winners
    float* outrow = hsparse + (size_t)row * NDIM;
    for (int i = tid; i < NDIM / 4; i += TTHREADS) {
        unsigned u0 = keys[4*i+0], u1 = keys[4*i+1], u2 = keys[4*i+2], u3 = keys[4*i+3];
        float4 f;
        f.x = (u0 > T) ? val_of(u0) : 0.0f;
        f.y = (u1 > T) ? val_of(u1) : 0.0f;
        f.z = (u2 > T) ? val_of(u2) : 0.0f;
        f.w = (u3 > T) ? val_of(u3) : 0.0f;
        __stcs(reinterpret_cast<float4*>(outrow) + i, f);
        unsigned us[4] = {u0, u1, u2, u3};
#pragma unroll
        for (int c = 0; c < 4; c++) {
            if (us[c] > T) {
                unsigned slot = atomicAdd(&s_ngt, 1u);
                g_idx[row * KSEL + slot] = 4 * i + c;
                g_val[row * KSEL + slot] = val_of(us[c]);
            } else if (us[c] == T) {
                unsigned p = atomicAdd(&s_neq, 1u);
                if (p < EQCAP) eqlst[p] = (unsigned)(4 * i + c);
            }
        }
    }
    __syncthreads();

    // resolve ties deterministically: first `needeq` ==T elements by index
    if (tid == 0) {
        const float tv = val_of(T);
        unsigned base = s_ngt;
        unsigned ne = s_neq;
        if (ne <= EQCAP) {
            for (unsigned a = 1; a < ne; a++) {
                unsigned v = eqlst[a]; int b = (int)a - 1;
                while (b >= 0 && eqlst[b] > v) { eqlst[b+1] = eqlst[b]; b--; }
                eqlst[b+1] = v;
            }
            for (unsigned t = 0; t < needeq; t++) {
                unsigned idx = eqlst[t];
                g_idx[row * KSEL + base + t] = (int)idx;
                g_val[row * KSEL + base + t] = tv;
                outrow[idx] = tv;
            }
        } else {
            unsigned got = 0;
            for (int i = 0; i < NDIM && got < needeq; i++) {
                if (keys[i] == T) {
                    g_idx[row * KSEL + base + got] = i;
                    g_val[row * KSEL + base + got] = tv;
                    outrow[i] = tv;
                    got++;
                }
            }
        }
    }
}

// ---------------- sparse decode (separate kernel) -------------------------------
__global__ __launch_bounds__(256) void decode_kernel(const float* __restrict__ bdec,
                                                     float* __restrict__ xhat) {
    __shared__ int   sidx[KSEL];
    __shared__ float sval[KSEL];
    const int row = blockIdx.x;
    const int tid = threadIdx.x;
    if (tid < KSEL) {
        int   idx = g_idx[row * KSEL + tid];
        float v   = g_val[row * KSEL + tid];
        int rank = 0;
#pragma unroll
        for (int j = 0; j < KSEL; j++) {
            int oj = __shfl_sync(0xFFFFFFFFu, idx, j);
            rank += (oj < idx);
        }
        sidx[rank] = idx;
        sval[rank] = v;
    }
    __syncthreads();
    float4 acc = reinterpret_cast<const float4*>(bdec)[tid];
#pragma unroll
    for (int j = 0; j < KSEL; j++) {
        float v = sval[j];
        float4 w = reinterpret_cast<const float4*>(g_wdt + (size_t)sidx[j] * DDIM)[tid];
        acc.x += v * w.x; acc.y += v * w.y; acc.z += v * w.z; acc.w += v * w.w;
    }
    reinterpret_cast<float4*>(xhat)[(size_t)row * 256 + tid] = acc;
}

// ---------------- launch ------------------------------------------------------
extern "C" void kernel_launch(void* const* d_in, const int* in_sizes, int n_in,
                              void* d_out, int out_size) {
    const float* x    = (const float*)d_in[0];
    const float* Wenc = (const float*)d_in[1];
    const float* benc = (const float*)d_in[2];
    const float* Wdec = (const float*)d_in[3];
    const float* bdec = (const float*)d_in[4];

    float* out  = (float*)d_out;
    float* xhat = out;
    float* hsp  = out + (size_t)BATCH * DDIM;
    float* hpre = hsp + (size_t)BATCH * NDIM;

    cudaFuncSetAttribute(gemm_mma_kernel, cudaFuncAttributeMaxDynamicSharedMemorySize, GEMM_SMEM);
    cudaFuncSetAttribute(topk_kernel,     cudaFuncAttributeMaxDynamicSharedMemorySize, TOPK_SMEM);

    prep_kernel<<<36864, 256>>>(x, bdec, Wenc, Wdec);
    gemm_mma_kernel<<<4096, 256, GEMM_SMEM>>>(benc, hpre);
    topk_kernel<<<BATCH, TTHREADS, TOPK_SMEM>>>(hpre, hsp);
    decode_kernel<<<BATCH, 256>>>(bdec, xhat);
}

// round 15
// speedup vs baseline: 1.0205x; 1.0205x over previous
#include <cuda_runtime.h>
#include <cuda_fp16.h>
#include <cstdint>

#define BATCH 4096
#define DDIM  1024
#define NDIM  16384
#define KSEL  32

// ---------------- scratch ----------------------------------------------------
__device__ __align__(256) unsigned short g_a0[BATCH * DDIM];
__device__ __align__(256) unsigned short g_a1[BATCH * DDIM];
__device__ __align__(256) unsigned short g_b0[NDIM * DDIM];
__device__ __align__(256) unsigned short g_b1[NDIM * DDIM];
__device__ float g_wdt[NDIM * DDIM];
__device__ int   g_idx[BATCH * KSEL];
__device__ float g_val[BATCH * KSEL];

// ---------------- helpers ------------------------------------------------------
__device__ __forceinline__ uint32_t smem_u32(const void* p) {
    uint32_t a;
    asm("{ .reg .u64 t; cvta.to.shared.u64 t, %1; cvt.u32.u64 %0, t; }" : "=r"(a) : "l"(p));
    return a;
}
__device__ __forceinline__ void cp_async16(uint32_t dst, const void* src) {
    asm volatile("cp.async.cg.shared.global [%0], [%1], 16;" :: "r"(dst), "l"(src));
}
#define LDSM_X4(R, addr) \
    asm volatile("ldmatrix.sync.aligned.m8n8.x4.shared.b16 {%0,%1,%2,%3}, [%4];" \
        : "=r"((R)[0]), "=r"((R)[1]), "=r"((R)[2]), "=r"((R)[3]) : "r"(addr))

__device__ __forceinline__ void mma16816(float* c, const uint32_t* a, const uint32_t* b) {
    asm volatile("mma.sync.aligned.m16n8k16.row.col.f32.f16.f16.f32 "
        "{%0,%1,%2,%3}, {%4,%5,%6,%7}, {%8,%9}, {%0,%1,%2,%3};"
        : "+f"(c[0]), "+f"(c[1]), "+f"(c[2]), "+f"(c[3])
        : "r"(a[0]), "r"(a[1]), "r"(a[2]), "r"(a[3]), "r"(b[0]), "r"(b[1]));
}

// ---------------- split conversion (fp16 2-term) ------------------------------
__device__ __forceinline__ void split2(float a, unsigned short& h0, unsigned short& h1) {
    __half b0 = __float2half_rn(a);
    float r = a - __half2float(b0);
    __half b1 = __float2half_rn(r);
    h0 = __half_as_ushort(b0);
    h1 = __half_as_ushort(b1);
}

// ---------------- prep: convA + convB (transpose split out) -------------------
__global__ __launch_bounds__(256) void prep_kernel(const float* __restrict__ x,
                                                   const float* __restrict__ bdec,
                                                   const float* __restrict__ wenc) {
    const int b = blockIdx.x;
    const int tid = threadIdx.x;
    if (b < 4096) {
        int i = b * 256 + tid;
        float4 xv = reinterpret_cast<const float4*>(x)[i];
        float4 bv = reinterpret_cast<const float4*>(bdec)[i & 255];
        float a[4] = {xv.x - bv.x, xv.y - bv.y, xv.z - bv.z, xv.w - bv.w};
        ushort4 o0, o1;
        split2(a[0], o0.x, o1.x); split2(a[1], o0.y, o1.y);
        split2(a[2], o0.z, o1.z); split2(a[3], o0.w, o1.w);
        reinterpret_cast<ushort4*>(g_a0)[i] = o0;
        reinterpret_cast<ushort4*>(g_a1)[i] = o1;
    } else {
        int i = (b - 4096) * 256 + tid;
        float4 xv = reinterpret_cast<const float4*>(wenc)[i];
        float a[4] = {xv.x, xv.y, xv.z, xv.w};
        ushort4 o0, o1;
        split2(a[0], o0.x, o1.x); split2(a[1], o0.y, o1.y);
        split2(a[2], o0.z, o1.z); split2(a[3], o0.w, o1.w);
        reinterpret_cast<ushort4*>(g_b0)[i] = o0;
        reinterpret_cast<ushort4*>(g_b1)[i] = o1;
    }
}

// ---------------- transpose W_dec [D,N] -> g_wdt [N,D] (overlaps GEMM) --------
__global__ void transpose_kernel(const float* __restrict__ w) {
    __shared__ float tile[32][33];
    int n  = blockIdx.x * 32 + threadIdx.x;
    int d0 = blockIdx.y * 32;
#pragma unroll
    for (int i = threadIdx.y; i < 32; i += 8)
        tile[i][threadIdx.x] = w[(size_t)(d0 + i) * NDIM + n];
    __syncthreads();
    int d  = d0 + threadIdx.x;
    int n0 = blockIdx.x * 32;
#pragma unroll
    for (int i = threadIdx.y; i < 32; i += 8)
        g_wdt[(size_t)(n0 + i) * DDIM + d] = tile[threadIdx.x][i];
}

// ---------------- mma.sync GEMM: h_pre = (x-b_dec) @ W_enc^T + b_enc ---------
// R7 inner loop (known-good: 872us, tensor 78.3%)
#define TILE_B   (128 * 64)
#define STAGE_B  (4 * TILE_B)
#define GEMM_SMEM (3 * STAGE_B)

__device__ __forceinline__ uint32_t swz(int r, int s) {
    return (uint32_t)(r * 64 + ((s ^ ((r >> 1) & 3)) << 4));
}

__global__ __launch_bounds__(256, 2) void gemm_mma_kernel(const float* __restrict__ benc,
                                                          float* __restrict__ hpre) {
    extern __shared__ unsigned char smem[];
    __shared__ float sbenc[128];
    const uint32_t sb = smem_u32(smem);
    const int tid  = threadIdx.x;
    const int wid  = tid >> 5;
    const int lane = tid & 31;

    const int bid  = blockIdx.x;
    const int band = bid >> 11;
    const int rr   = bid & 2047;
    const int nb   = rr >> 4;
    const int mb   = (band << 4) + (rr & 15);
    const int m0 = mb * 128, n0 = nb * 128;

    if (tid < 128) sbenc[tid] = benc[n0 + tid];

    const unsigned short* srcs[4] = {
        g_a0 + (size_t)m0 * DDIM, g_a1 + (size_t)m0 * DDIM,
        g_b0 + (size_t)n0 * DDIM, g_b1 + (size_t)n0 * DDIM };

    auto load_stage = [&](int kt) {
        const uint32_t base = sb + (uint32_t)(kt % 3) * STAGE_B;
#pragma unroll
        for (int t = 0; t < 4; t++) {
            const unsigned short* src = srcs[t] + kt * 32;
#pragma unroll
            for (int i = 0; i < 2; i++) {
                int id = tid + i * 256;
                int row = id >> 2, seg = id & 3;
                cp_async16(base + (uint32_t)t * TILE_B + swz(row, seg),
                           src + (size_t)row * DDIM + seg * 8);
            }
        }
        asm volatile("cp.async.commit_group;" ::: "memory");
    };

    float c[4][4][4];
#pragma unroll
    for (int i = 0; i < 4; i++)
#pragma unroll
        for (int j = 0; j < 4; j++)
#pragma unroll
            for (int q = 0; q < 4; q++) c[i][j][q] = 0.0f;

    const int wm = wid & 1;
    const int wn = wid >> 1;

    const int a_row = wm * 64 + (lane & 15);
    const int a_hi  = lane >> 4;
    const int b_row = wn * 32 + (lane & 7) + ((lane >> 4) << 3);
    const int b_hi  = (lane >> 3) & 1;

    load_stage(0);
    load_stage(1);

    for (int kt = 0; kt < 32; kt++) {
        if (kt < 31) asm volatile("cp.async.wait_group 1;" ::: "memory");
        else         asm volatile("cp.async.wait_group 0;" ::: "memory");
        __syncthreads();
        if (kt + 2 < 32) load_stage(kt + 2);

        const uint32_t base = sb + (uint32_t)(kt % 3) * STAGE_B;
        const uint32_t aB0 = base, aB1 = base + TILE_B;
        const uint32_t bB0 = base + 2 * TILE_B, bB1 = base + 3 * TILE_B;

#pragma unroll
        for (int kk = 0; kk < 2; kk++) {
            uint32_t b0f[4][2], b1f[4][2];
#pragma unroll
            for (int p = 0; p < 2; p++) {
                uint32_t off = swz(b_row + p * 16, kk * 2 + b_hi);
                uint32_t r4[4];
                LDSM_X4(r4, bB0 + off);
                b0f[2*p][0] = r4[0]; b0f[2*p][1] = r4[1];
                b0f[2*p+1][0] = r4[2]; b0f[2*p+1][1] = r4[3];
                LDSM_X4(r4, bB1 + off);
                b1f[2*p][0] = r4[0]; b1f[2*p][1] = r4[1];
                b1f[2*p+1][0] = r4[2]; b1f[2*p+1][1] = r4[3];
            }
#pragma unroll
            for (int mi = 0; mi < 4; mi++) {
                uint32_t a0f[4], a1f[4];
                uint32_t off = swz(a_row + mi * 16, kk * 2 + a_hi);
                LDSM_X4(a0f, aB0 + off);
                LDSM_X4(a1f, aB1 + off);
#pragma unroll
                for (int ni = 0; ni < 4; ni++) {
                    mma16816(c[mi][ni], a0f, b0f[ni]);
                    mma16816(c[mi][ni], a0f, b1f[ni]);
                    mma16816(c[mi][ni], a1f, b0f[ni]);
                }
            }
        }
    }
    __syncthreads();

    const int erow = m0 + wm * 64 + (lane >> 2);
    const int ecol0 = wn * 32 + (lane & 3) * 2;
#pragma unroll
    for (int mi = 0; mi < 4; mi++) {
#pragma unroll
        for (int ni = 0; ni < 4; ni++) {
            const int col = ecol0 + ni * 8;
            const float be0 = sbenc[col], be1 = sbenc[col + 1];
            float* p0 = hpre + (size_t)(erow + mi * 16) * NDIM + n0 + col;
            float* p1 = hpre + (size_t)(erow + mi * 16 + 8) * NDIM + n0 + col;
            float2 v0 = {c[mi][ni][0] + be0, c[mi][ni][1] + be1};
            float2 v1 = {c[mi][ni][2] + be0, c[mi][ni][3] + be1};
            __stcs(reinterpret_cast<float2*>(p0), v0);
            __stcs(reinterpret_cast<float2*>(p1), v1);
        }
    }
}

// ---------------- top-k: R13 champion (512 threads, 3 CTAs/SM) ----------------
#define CAND_MAX 2048
#define EQCAP    256
#define TOPK_SMEM ((NDIM + 256 + 32 + CAND_MAX + EQCAP) * 4)
#define TTHREADS 512

__device__ __forceinline__ void suffix_scan256_w16(unsigned val, volatile unsigned* shm32,
                                                   int tid, unsigned& ge, unsigned& gt) {
    const int lane = tid & 31;
    const int wid  = tid >> 5;
    unsigned v = val;
    if (wid < 8) {
#pragma unroll
        for (int off = 1; off < 32; off <<= 1) {
            unsigned t = __shfl_down_sync(0xFFFFFFFFu, v, off);
            if (lane + off < 32) v += t;
        }
        if (lane == 0) shm32[wid] = v;
    }
    __syncthreads();
    if (wid == 0) {
        unsigned w = (lane < 8) ? shm32[lane] : 0u;
        unsigned u = w;
#pragma unroll
        for (int off = 1; off < 8; off <<= 1) {
            unsigned t = __shfl_down_sync(0xFFFFFFFFu, u, off);
            if (lane + off < 8) u += t;
        }
        if (lane < 8) shm32[16 + lane] = u - w;
    }
    __syncthreads();
    if (wid < 8) {
        unsigned tx = shm32[16 + wid];
        v += tx;
        ge = v;
        unsigned nv = __shfl_down_sync(0xFFFFFFFFu, v, 1);
        gt = (lane < 31) ? nv : tx;
    } else {
        ge = 0; gt = 0;
    }
}

__device__ __forceinline__ unsigned key_xform(unsigned u) {
    return (u & 0x80000000u) ? ~u : (u | 0x80000000u);
}
__device__ __forceinline__ float val_of(unsigned u) {
    return __uint_as_float((u >> 31) ? (u ^ 0x80000000u) : ~u);
}

__global__ __launch_bounds__(TTHREADS, 3) void topk_kernel(const float* __restrict__ hpre,
                                                           float* __restrict__ hsparse) {
    extern __shared__ unsigned sm[];
    unsigned* keys  = sm;                      // 16384
    unsigned* hist  = sm + NDIM;               // 256
    unsigned* shm32 = hist + 256;              // 32
    unsigned* ckey  = shm32 + 32;              // CAND_MAX
    unsigned* eqlst = ckey + CAND_MAX;         // EQCAP
    __shared__ unsigned s_b, s_kr, s_nc, s_ngt, s_neq;
    const int row = blockIdx.x;
    const int tid = threadIdx.x;
    const int lane = tid & 31;
    const float* in = hpre + (size_t)row * NDIM;
    const uint32_t keys_sm = smem_u32(keys);

#pragma unroll
    for (int i = 0; i < 8; i++) {
        int c = tid + i * TTHREADS;
        cp_async16(keys_sm + (uint32_t)c * 16u, in + c * 4);
    }
    asm volatile("cp.async.commit_group;" ::: "memory");
    if (tid < 256) hist[tid] = 0;
    if (tid == 0) { s_nc = 0; s_ngt = 0; s_neq = 0; }
    asm volatile("cp.async.wait_group 0;" ::: "memory");
    __syncthreads();

    for (int i = tid; i < NDIM / 4; i += TTHREADS) {
        uint4 r = reinterpret_cast<uint4*>(keys)[i];
        unsigned u0 = key_xform(r.x), u1 = key_xform(r.y);
        unsigned u2 = key_xform(r.z), u3 = key_xform(r.w);
        uint4 o = {u0, u1, u2, u3};
        reinterpret_cast<uint4*>(keys)[i] = o;
        unsigned bins[4] = {u0 >> 24, u1 >> 24, u2 >> 24, u3 >> 24};
#pragma unroll
        for (int c = 0; c < 4; c++) {
            unsigned msk = __match_any_sync(0xFFFFFFFFu, bins[c]);
            if (lane == (__ffs(msk) - 1)) atomicAdd(&hist[bins[c]], __popc(msk));
        }
    }
    __syncthreads();
    {
        unsigned ge, gt;
        unsigned hv = (tid < 256) ? hist[tid] : 0u;
        suffix_scan256_w16(hv, shm32, tid, ge, gt);
        if (tid < 256 && gt < KSEL && KSEL <= ge) { s_b = (unsigned)tid; s_kr = KSEL - gt; }
    }
    __syncthreads();
    const unsigned topbyte = s_b;
    unsigned krem = s_kr;

    for (int i = tid; i < NDIM / 4; i += TTHREADS) {
        uint4 r = reinterpret_cast<uint4*>(keys)[i];
        unsigned us[4] = {r.x, r.y, r.z, r.w};
#pragma unroll
        for (int c = 0; c < 4; c++) {
            bool p = (us[c] >> 24) == topbyte;
            unsigned ball = __ballot_sync(0xFFFFFFFFu, p);
            unsigned base = 0;
            if (lane == 0 && ball) base = atomicAdd(&s_nc, (unsigned)__popc(ball));
            base = __shfl_sync(0xFFFFFFFFu, base, 0);
            if (p) {
                unsigned pos = base + __popc(ball & ((1u << lane) - 1u));
                if (pos < CAND_MAX) ckey[pos] = us[c];
            }
        }
    }
    __syncthreads();
    const bool overflow = (s_nc > (unsigned)CAND_MAX);
    const unsigned* csrc = overflow ? keys : ckey;
    const unsigned nc = overflow ? (unsigned)NDIM : s_nc;

    unsigned prefix = topbyte << 24, pmask = 0xFF000000u;
    for (int shift = 16; shift >= 0; shift -= 8) {
        if (tid < 256) hist[tid] = 0;
        __syncthreads();
        for (unsigned j = tid; j < nc; j += TTHREADS) {
            unsigned u = csrc[j];
            if ((u & pmask) == prefix) atomicAdd(&hist[(u >> shift) & 255], 1u);
        }
        __syncthreads();
        unsigned ge, gt;
        unsigned hv = (tid < 256) ? hist[tid] : 0u;
        suffix_scan256_w16(hv, shm32, tid, ge, gt);
        if (tid < 256 && gt < krem && krem <= ge) { s_b = (unsigned)tid; s_kr = krem - gt; }
        __syncthreads();
        prefix |= (s_b << shift);
        pmask  |= (0xFFu << shift);
        krem = s_kr;
        __syncthreads();
    }
    const unsigned T = prefix;
    const unsigned needeq = krem;

    float* outrow = hsparse + (size_t)row * NDIM;
    for (int i = tid; i < NDIM / 4; i += TTHREADS) {
        unsigned u0 = keys[4*i+0], u1 = keys[4*i+1], u2 = keys[4*i+2], u3 = keys[4*i+3];
        float4 f;
        f.x = (u0 > T) ? val_of(u0) : 0.0f;
        f.y = (u1 > T) ? val_of(u1) : 0.0f;
        f.z = (u2 > T) ? val_of(u2) : 0.0f;
        f.w = (u3 > T) ? val_of(u3) : 0.0f;
        __stcs(reinterpret_cast<float4*>(outrow) + i, f);
        unsigned us[4] = {u0, u1, u2, u3};
#pragma unroll
        for (int c = 0; c < 4; c++) {
            if (us[c] > T) {
                unsigned slot = atomicAdd(&s_ngt, 1u);
                g_idx[row * KSEL + slot] = 4 * i + c;
                g_val[row * KSEL + slot] = val_of(us[c]);
            } else if (us[c] == T) {
                unsigned p = atomicAdd(&s_neq, 1u);
                if (p < EQCAP) eqlst[p] = (unsigned)(4 * i + c);
            }
        }
    }
    __syncthreads();

    if (tid == 0) {
        const float tv = val_of(T);
        unsigned base = s_ngt;
        unsigned ne = s_neq;
        if (ne <= EQCAP) {
            for (unsigned a = 1; a < ne; a++) {
                unsigned v = eqlst[a]; int b = (int)a - 1;
                while (b >= 0 && eqlst[b] > v) { eqlst[b+1] = eqlst[b]; b--; }
                eqlst[b+1] = v;
            }
            for (unsigned t = 0; t < needeq; t++) {
                unsigned idx = eqlst[t];
                g_idx[row * KSEL + base + t] = (int)idx;
                g_val[row * KSEL + base + t] = tv;
                outrow[idx] = tv;
            }
        } else {
            unsigned got = 0;
            for (int i = 0; i < NDIM && got < needeq; i++) {
                if (keys[i] == T) {
                    g_idx[row * KSEL + base + got] = i;
                    g_val[row * KSEL + base + got] = tv;
                    outrow[i] = tv;
                    got++;
                }
            }
        }
    }
}

// ---------------- sparse decode (separate kernel) -------------------------------
__global__ __launch_bounds__(256) void decode_kernel(const float* __restrict__ bdec,
                                                     float* __restrict__ xhat) {
    __shared__ int   sidx[KSEL];
    __shared__ float sval[KSEL];
    const int row = blockIdx.x;
    const int tid = threadIdx.x;
    if (tid < KSEL) {
        int   idx = g_idx[row * KSEL + tid];
        float v   = g_val[row * KSEL + tid];
        int rank = 0;
#pragma unroll
        for (int j = 0; j < KSEL; j++) {
            int oj = __shfl_sync(0xFFFFFFFFu, idx, j);
            rank += (oj < idx);
        }
        sidx[rank] = idx;
        sval[rank] = v;
    }
    __syncthreads();
    float4 acc = reinterpret_cast<const float4*>(bdec)[tid];
#pragma unroll
    for (int j = 0; j < KSEL; j++) {
        float v = sval[j];
        float4 w = reinterpret_cast<const float4*>(g_wdt + (size_t)sidx[j] * DDIM)[tid];
        acc.x += v * w.x; acc.y += v * w.y; acc.z += v * w.z; acc.w += v * w.w;
    }
    reinterpret_cast<float4*>(xhat)[(size_t)row * 256 + tid] = acc;
}

// ---------------- streams/events (host objects, created once at init) ----------
namespace {
struct Aux {
    cudaStream_t s1 = nullptr;
    cudaEvent_t  evFork = nullptr;
    cudaEvent_t  evJoin = nullptr;
    Aux() {
        cudaStreamCreateWithFlags(&s1, cudaStreamNonBlocking);
        cudaEventCreateWithFlags(&evFork, cudaEventDisableTiming);
        cudaEventCreateWithFlags(&evJoin, cudaEventDisableTiming);
    }
};
Aux g_aux;
}

// ---------------- launch ------------------------------------------------------
extern "C" void kernel_launch(void* const* d_in, const int* in_sizes, int n_in,
                              void* d_out, int out_size) {
    const float* x    = (const float*)d_in[0];
    const float* Wenc = (const float*)d_in[1];
    const float* benc = (const float*)d_in[2];
    const float* Wdec = (const float*)d_in[3];
    const float* bdec = (const float*)d_in[4];

    float* out  = (float*)d_out;
    float* xhat = out;
    float* hsp  = out + (size_t)BATCH * DDIM;
    float* hpre = hsp + (size_t)BATCH * NDIM;

    cudaFuncSetAttribute(gemm_mma_kernel, cudaFuncAttributeMaxDynamicSharedMemorySize, GEMM_SMEM);
    cudaFuncSetAttribute(topk_kernel,     cudaFuncAttributeMaxDynamicSharedMemorySize, TOPK_SMEM);

    // fork: W_dec transpose is independent of prep/GEMM/topk — overlap it
    cudaEventRecord(g_aux.evFork, 0);
    cudaStreamWaitEvent(g_aux.s1, g_aux.evFork, 0);
    transpose_kernel<<<dim3(NDIM / 32, DDIM / 32), dim3(32, 8), 0, g_aux.s1>>>(Wdec);
    cudaEventRecord(g_aux.evJoin, g_aux.s1);

    prep_kernel<<<20480, 256>>>(x, bdec, Wenc);
    gemm_mma_kernel<<<4096, 256, GEMM_SMEM>>>(benc, hpre);
    topk_kernel<<<BATCH, TTHREADS, TOPK_SMEM>>>(hpre, hsp);

    // join: decode needs g_wdt
    cudaStreamWaitEvent(0, g_aux.evJoin, 0);
    decode_kernel<<<BATCH, 256>>>(bdec, xhat);
}

// round 16
// speedup vs baseline: 1.0245x; 1.0039x over previous
#include <cuda_runtime.h>
#include <cuda_fp16.h>
#include <cstdint>

#define BATCH 4096
#define DDIM  1024
#define NDIM  16384
#define KSEL  32

// ---------------- scratch ----------------------------------------------------
__device__ __align__(256) unsigned short g_a0[BATCH * DDIM];
__device__ __align__(256) unsigned short g_a1[BATCH * DDIM];
__device__ __align__(256) unsigned short g_b0[NDIM * DDIM];
__device__ __align__(256) unsigned short g_b1[NDIM * DDIM];
__device__ float g_wdt[NDIM * DDIM];
__device__ int   g_idx[BATCH * KSEL];
__device__ float g_val[BATCH * KSEL];

// ---------------- helpers ------------------------------------------------------
__device__ __forceinline__ uint32_t smem_u32(const void* p) {
    uint32_t a;
    asm("{ .reg .u64 t; cvta.to.shared.u64 t, %1; cvt.u32.u64 %0, t; }" : "=r"(a) : "l"(p));
    return a;
}
__device__ __forceinline__ void cp_async16(uint32_t dst, const void* src) {
    asm volatile("cp.async.cg.shared.global [%0], [%1], 16;" :: "r"(dst), "l"(src));
}
#define LDSM_X4(R, addr) \
    asm volatile("ldmatrix.sync.aligned.m8n8.x4.shared.b16 {%0,%1,%2,%3}, [%4];" \
        : "=r"((R)[0]), "=r"((R)[1]), "=r"((R)[2]), "=r"((R)[3]) : "r"(addr))

__device__ __forceinline__ void mma16816(float* c, const uint32_t* a, const uint32_t* b) {
    asm volatile("mma.sync.aligned.m16n8k16.row.col.f32.f16.f16.f32 "
        "{%0,%1,%2,%3}, {%4,%5,%6,%7}, {%8,%9}, {%0,%1,%2,%3};"
        : "+f"(c[0]), "+f"(c[1]), "+f"(c[2]), "+f"(c[3])
        : "r"(a[0]), "r"(a[1]), "r"(a[2]), "r"(a[3]), "r"(b[0]), "r"(b[1]));
}

// ---------------- split conversion (fp16 2-term) ------------------------------
__device__ __forceinline__ void split2(float a, unsigned short& h0, unsigned short& h1) {
    __half b0 = __float2half_rn(a);
    float r = a - __half2float(b0);
    __half b1 = __float2half_rn(r);
    h0 = __half_as_ushort(b0);
    h1 = __half_as_ushort(b1);
}

// ---------------- prep: convA + convB (transpose split out) -------------------
__global__ __launch_bounds__(256) void prep_kernel(const float* __restrict__ x,
                                                   const float* __restrict__ bdec,
                                                   const float* __restrict__ wenc) {
    const int b = blockIdx.x;
    const int tid = threadIdx.x;
    if (b < 4096) {
        int i = b * 256 + tid;
        float4 xv = reinterpret_cast<const float4*>(x)[i];
        float4 bv = reinterpret_cast<const float4*>(bdec)[i & 255];
        float a[4] = {xv.x - bv.x, xv.y - bv.y, xv.z - bv.z, xv.w - bv.w};
        ushort4 o0, o1;
        split2(a[0], o0.x, o1.x); split2(a[1], o0.y, o1.y);
        split2(a[2], o0.z, o1.z); split2(a[3], o0.w, o1.w);
        reinterpret_cast<ushort4*>(g_a0)[i] = o0;
        reinterpret_cast<ushort4*>(g_a1)[i] = o1;
    } else {
        int i = (b - 4096) * 256 + tid;
        float4 xv = reinterpret_cast<const float4*>(wenc)[i];
        float a[4] = {xv.x, xv.y, xv.z, xv.w};
        ushort4 o0, o1;
        split2(a[0], o0.x, o1.x); split2(a[1], o0.y, o1.y);
        split2(a[2], o0.z, o1.z); split2(a[3], o0.w, o1.w);
        reinterpret_cast<ushort4*>(g_b0)[i] = o0;
        reinterpret_cast<ushort4*>(g_b1)[i] = o1;
    }
}

// ---------------- transpose W_dec [D,N] -> g_wdt [N,D] (overlaps GEMM) --------
__global__ void transpose_kernel(const float* __restrict__ w) {
    __shared__ float tile[32][33];
    int n  = blockIdx.x * 32 + threadIdx.x;
    int d0 = blockIdx.y * 32;
#pragma unroll
    for (int i = threadIdx.y; i < 32; i += 8)
        tile[i][threadIdx.x] = w[(size_t)(d0 + i) * NDIM + n];
    __syncthreads();
    int d  = d0 + threadIdx.x;
    int n0 = blockIdx.x * 32;
#pragma unroll
    for (int i = threadIdx.y; i < 32; i += 8)
        g_wdt[(size_t)(n0 + i) * DDIM + d] = tile[threadIdx.x][i];
}

// ---------------- mma.sync GEMM: h_pre = (x-b_dec) @ W_enc^T + b_enc ---------
// R7 inner loop (known-good: 872us, tensor 78.3%)
#define TILE_B   (128 * 64)
#define STAGE_B  (4 * TILE_B)
#define GEMM_SMEM (3 * STAGE_B)

__device__ __forceinline__ uint32_t swz(int r, int s) {
    return (uint32_t)(r * 64 + ((s ^ ((r >> 1) & 3)) << 4));
}

__global__ __launch_bounds__(256, 2) void gemm_mma_kernel(const float* __restrict__ benc,
                                                          float* __restrict__ hpre) {
    extern __shared__ unsigned char smem[];
    __shared__ float sbenc[128];
    const uint32_t sb = smem_u32(smem);
    const int tid  = threadIdx.x;
    const int wid  = tid >> 5;
    const int lane = tid & 31;

    const int bid  = blockIdx.x;
    const int band = bid >> 11;
    const int rr   = bid & 2047;
    const int nb   = rr >> 4;
    const int mb   = (band << 4) + (rr & 15);
    const int m0 = mb * 128, n0 = nb * 128;

    if (tid < 128) sbenc[tid] = benc[n0 + tid];

    const unsigned short* srcs[4] = {
        g_a0 + (size_t)m0 * DDIM, g_a1 + (size_t)m0 * DDIM,
        g_b0 + (size_t)n0 * DDIM, g_b1 + (size_t)n0 * DDIM };

    auto load_stage = [&](int kt) {
        const uint32_t base = sb + (uint32_t)(kt % 3) * STAGE_B;
#pragma unroll
        for (int t = 0; t < 4; t++) {
            const unsigned short* src = srcs[t] + kt * 32;
#pragma unroll
            for (int i = 0; i < 2; i++) {
                int id = tid + i * 256;
                int row = id >> 2, seg = id & 3;
                cp_async16(base + (uint32_t)t * TILE_B + swz(row, seg),
                           src + (size_t)row * DDIM + seg * 8);
            }
        }
        asm volatile("cp.async.commit_group;" ::: "memory");
    };

    float c[4][4][4];
#pragma unroll
    for (int i = 0; i < 4; i++)
#pragma unroll
        for (int j = 0; j < 4; j++)
#pragma unroll
            for (int q = 0; q < 4; q++) c[i][j][q] = 0.0f;

    const int wm = wid & 1;
    const int wn = wid >> 1;

    const int a_row = wm * 64 + (lane & 15);
    const int a_hi  = lane >> 4;
    const int b_row = wn * 32 + (lane & 7) + ((lane >> 4) << 3);
    const int b_hi  = (lane >> 3) & 1;

    load_stage(0);
    load_stage(1);

    for (int kt = 0; kt < 32; kt++) {
        if (kt < 31) asm volatile("cp.async.wait_group 1;" ::: "memory");
        else         asm volatile("cp.async.wait_group 0;" ::: "memory");
        __syncthreads();
        if (kt + 2 < 32) load_stage(kt + 2);

        const uint32_t base = sb + (uint32_t)(kt % 3) * STAGE_B;
        const uint32_t aB0 = base, aB1 = base + TILE_B;
        const uint32_t bB0 = base + 2 * TILE_B, bB1 = base + 3 * TILE_B;

#pragma unroll
        for (int kk = 0; kk < 2; kk++) {
            uint32_t b0f[4][2], b1f[4][2];
#pragma unroll
            for (int p = 0; p < 2; p++) {
                uint32_t off = swz(b_row + p * 16, kk * 2 + b_hi);
                uint32_t r4[4];
                LDSM_X4(r4, bB0 + off);
                b0f[2*p][0] = r4[0]; b0f[2*p][1] = r4[1];
                b0f[2*p+1][0] = r4[2]; b0f[2*p+1][1] = r4[3];
                LDSM_X4(r4, bB1 + off);
                b1f[2*p][0] = r4[0]; b1f[2*p][1] = r4[1];
                b1f[2*p+1][0] = r4[2]; b1f[2*p+1][1] = r4[3];
            }
#pragma unroll
            for (int mi = 0; mi < 4; mi++) {
                uint32_t a0f[4], a1f[4];
                uint32_t off = swz(a_row + mi * 16, kk * 2 + a_hi);
                LDSM_X4(a0f, aB0 + off);
                LDSM_X4(a1f, aB1 + off);
#pragma unroll
                for (int ni = 0; ni < 4; ni++) {
                    mma16816(c[mi][ni], a0f, b0f[ni]);
                    mma16816(c[mi][ni], a0f, b1f[ni]);
                    mma16816(c[mi][ni], a1f, b0f[ni]);
                }
            }
        }
    }
    __syncthreads();

    const int erow = m0 + wm * 64 + (lane >> 2);
    const int ecol0 = wn * 32 + (lane & 3) * 2;
#pragma unroll
    for (int mi = 0; mi < 4; mi++) {
#pragma unroll
        for (int ni = 0; ni < 4; ni++) {
            const int col = ecol0 + ni * 8;
            const float be0 = sbenc[col], be1 = sbenc[col + 1];
            float* p0 = hpre + (size_t)(erow + mi * 16) * NDIM + n0 + col;
            float* p1 = hpre + (size_t)(erow + mi * 16 + 8) * NDIM + n0 + col;
            float2 v0 = {c[mi][ni][0] + be0, c[mi][ni][1] + be1};
            float2 v1 = {c[mi][ni][2] + be0, c[mi][ni][3] + be1};
            __stcs(reinterpret_cast<float2*>(p0), v0);
            __stcs(reinterpret_cast<float2*>(p1), v1);
        }
    }
}

// ---------------- top-k: R13 champion + vectorized sweep 3 ---------------------
#define CAND_MAX 2048
#define EQCAP    256
#define TOPK_SMEM ((NDIM + 256 + 32 + CAND_MAX + EQCAP) * 4)
#define TTHREADS 512

__device__ __forceinline__ void suffix_scan256_w16(unsigned val, volatile unsigned* shm32,
                                                   int tid, unsigned& ge, unsigned& gt) {
    const int lane = tid & 31;
    const int wid  = tid >> 5;
    unsigned v = val;
    if (wid < 8) {
#pragma unroll
        for (int off = 1; off < 32; off <<= 1) {
            unsigned t = __shfl_down_sync(0xFFFFFFFFu, v, off);
            if (lane + off < 32) v += t;
        }
        if (lane == 0) shm32[wid] = v;
    }
    __syncthreads();
    if (wid == 0) {
        unsigned w = (lane < 8) ? shm32[lane] : 0u;
        unsigned u = w;
#pragma unroll
        for (int off = 1; off < 8; off <<= 1) {
            unsigned t = __shfl_down_sync(0xFFFFFFFFu, u, off);
            if (lane + off < 8) u += t;
        }
        if (lane < 8) shm32[16 + lane] = u - w;
    }
    __syncthreads();
    if (wid < 8) {
        unsigned tx = shm32[16 + wid];
        v += tx;
        ge = v;
        unsigned nv = __shfl_down_sync(0xFFFFFFFFu, v, 1);
        gt = (lane < 31) ? nv : tx;
    } else {
        ge = 0; gt = 0;
    }
}

__device__ __forceinline__ unsigned key_xform(unsigned u) {
    return (u & 0x80000000u) ? ~u : (u | 0x80000000u);
}
__device__ __forceinline__ float val_of(unsigned u) {
    return __uint_as_float((u >> 31) ? (u ^ 0x80000000u) : ~u);
}

__global__ __launch_bounds__(TTHREADS, 3) void topk_kernel(const float* __restrict__ hpre,
                                                           float* __restrict__ hsparse) {
    extern __shared__ unsigned sm[];
    unsigned* keys  = sm;                      // 16384
    unsigned* hist  = sm + NDIM;               // 256
    unsigned* shm32 = hist + 256;              // 32
    unsigned* ckey  = shm32 + 32;              // CAND_MAX
    unsigned* eqlst = ckey + CAND_MAX;         // EQCAP
    __shared__ unsigned s_b, s_kr, s_nc, s_ngt, s_neq;
    const int row = blockIdx.x;
    const int tid = threadIdx.x;
    const int lane = tid & 31;
    const float* in = hpre + (size_t)row * NDIM;
    const uint32_t keys_sm = smem_u32(keys);

#pragma unroll
    for (int i = 0; i < 8; i++) {
        int c = tid + i * TTHREADS;
        cp_async16(keys_sm + (uint32_t)c * 16u, in + c * 4);
    }
    asm volatile("cp.async.commit_group;" ::: "memory");
    if (tid < 256) hist[tid] = 0;
    if (tid == 0) { s_nc = 0; s_ngt = 0; s_neq = 0; }
    asm volatile("cp.async.wait_group 0;" ::: "memory");
    __syncthreads();

    // sweep 1: transform in place + histogram top byte (warp-aggregated)
    for (int i = tid; i < NDIM / 4; i += TTHREADS) {
        uint4 r = reinterpret_cast<uint4*>(keys)[i];
        unsigned u0 = key_xform(r.x), u1 = key_xform(r.y);
        unsigned u2 = key_xform(r.z), u3 = key_xform(r.w);
        uint4 o = {u0, u1, u2, u3};
        reinterpret_cast<uint4*>(keys)[i] = o;
        unsigned bins[4] = {u0 >> 24, u1 >> 24, u2 >> 24, u3 >> 24};
#pragma unroll
        for (int c = 0; c < 4; c++) {
            unsigned msk = __match_any_sync(0xFFFFFFFFu, bins[c]);
            if (lane == (__ffs(msk) - 1)) atomicAdd(&hist[bins[c]], __popc(msk));
        }
    }
    __syncthreads();
    {
        unsigned ge, gt;
        unsigned hv = (tid < 256) ? hist[tid] : 0u;
        suffix_scan256_w16(hv, shm32, tid, ge, gt);
        if (tid < 256 && gt < KSEL && KSEL <= ge) { s_b = (unsigned)tid; s_kr = KSEL - gt; }
    }
    __syncthreads();
    const unsigned topbyte = s_b;
    unsigned krem = s_kr;

    // sweep 2: ballot-aggregated compaction
    for (int i = tid; i < NDIM / 4; i += TTHREADS) {
        uint4 r = reinterpret_cast<uint4*>(keys)[i];
        unsigned us[4] = {r.x, r.y, r.z, r.w};
#pragma unroll
        for (int c = 0; c < 4; c++) {
            bool p = (us[c] >> 24) == topbyte;
            unsigned ball = __ballot_sync(0xFFFFFFFFu, p);
            unsigned base = 0;
            if (lane == 0 && ball) base = atomicAdd(&s_nc, (unsigned)__popc(ball));
            base = __shfl_sync(0xFFFFFFFFu, base, 0);
            if (p) {
                unsigned pos = base + __popc(ball & ((1u << lane) - 1u));
                if (pos < CAND_MAX) ckey[pos] = us[c];
            }
        }
    }
    __syncthreads();
    const bool overflow = (s_nc > (unsigned)CAND_MAX);
    const unsigned* csrc = overflow ? keys : ckey;
    const unsigned nc = overflow ? (unsigned)NDIM : s_nc;

    // passes 2-4 over candidates only
    unsigned prefix = topbyte << 24, pmask = 0xFF000000u;
    for (int shift = 16; shift >= 0; shift -= 8) {
        if (tid < 256) hist[tid] = 0;
        __syncthreads();
        for (unsigned j = tid; j < nc; j += TTHREADS) {
            unsigned u = csrc[j];
            if ((u & pmask) == prefix) atomicAdd(&hist[(u >> shift) & 255], 1u);
        }
        __syncthreads();
        unsigned ge, gt;
        unsigned hv = (tid < 256) ? hist[tid] : 0u;
        suffix_scan256_w16(hv, shm32, tid, ge, gt);
        if (tid < 256 && gt < krem && krem <= ge) { s_b = (unsigned)tid; s_kr = krem - gt; }
        __syncthreads();
        prefix |= (s_b << shift);
        pmask  |= (0xFFu << shift);
        krem = s_kr;
        __syncthreads();
    }
    const unsigned T = prefix;
    const unsigned needeq = krem;

    // sweep 3: vectorized loads, write h_sparse (streaming) + collect winners
    float* outrow = hsparse + (size_t)row * NDIM;
    for (int i = tid; i < NDIM / 4; i += TTHREADS) {
        uint4 r = reinterpret_cast<uint4*>(keys)[i];
        unsigned us[4] = {r.x, r.y, r.z, r.w};
        float4 f;
        f.x = (us[0] > T) ? val_of(us[0]) : 0.0f;
        f.y = (us[1] > T) ? val_of(us[1]) : 0.0f;
        f.z = (us[2] > T) ? val_of(us[2]) : 0.0f;
        f.w = (us[3] > T) ? val_of(us[3]) : 0.0f;
        __stcs(reinterpret_cast<float4*>(outrow) + i, f);
#pragma unroll
        for (int c = 0; c < 4; c++) {
            if (us[c] > T) {
                unsigned slot = atomicAdd(&s_ngt, 1u);
                g_idx[row * KSEL + slot] = 4 * i + c;
                g_val[row * KSEL + slot] = val_of(us[c]);
            } else if (us[c] == T) {
                unsigned p = atomicAdd(&s_neq, 1u);
                if (p < EQCAP) eqlst[p] = (unsigned)(4 * i + c);
            }
        }
    }
    __syncthreads();

    // resolve ties deterministically: first `needeq` ==T elements by index
    if (tid == 0) {
        const float tv = val_of(T);
        unsigned base = s_ngt;
        unsigned ne = s_neq;
        if (ne <= EQCAP) {
            for (unsigned a = 1; a < ne; a++) {
                unsigned v = eqlst[a]; int b = (int)a - 1;
                while (b >= 0 && eqlst[b] > v) { eqlst[b+1] = eqlst[b]; b--; }
                eqlst[b+1] = v;
            }
            for (unsigned t = 0; t < needeq; t++) {
                unsigned idx = eqlst[t];
                g_idx[row * KSEL + base + t] = (int)idx;
                g_val[row * KSEL + base + t] = tv;
                outrow[idx] = tv;
            }
        } else {
            unsigned got = 0;
            for (int i = 0; i < NDIM && got < needeq; i++) {
                if (keys[i] == T) {
                    g_idx[row * KSEL + base + got] = i;
                    g_val[row * KSEL + base + got] = tv;
                    outrow[i] = tv;
                    got++;
                }
            }
        }
    }
}

// ---------------- sparse decode (separate kernel) -------------------------------
__global__ __launch_bounds__(256) void decode_kernel(const float* __restrict__ bdec,
                                                     float* __restrict__ xhat) {
    __shared__ int   sidx[KSEL];
    __shared__ float sval[KSEL];
    const int row = blockIdx.x;
    const int tid = threadIdx.x;
    if (tid < KSEL) {
        int   idx = g_idx[row * KSEL + tid];
        float v   = g_val[row * KSEL + tid];
        int rank = 0;
#pragma unroll
        for (int j = 0; j < KSEL; j++) {
            int oj = __shfl_sync(0xFFFFFFFFu, idx, j);
            rank += (oj < idx);
        }
        sidx[rank] = idx;
        sval[rank] = v;
    }
    __syncthreads();
    float4 acc = reinterpret_cast<const float4*>(bdec)[tid];
#pragma unroll
    for (int j = 0; j < KSEL; j++) {
        float v = sval[j];
        float4 w = reinterpret_cast<const float4*>(g_wdt + (size_t)sidx[j] * DDIM)[tid];
        acc.x += v * w.x; acc.y += v * w.y; acc.z += v * w.z; acc.w += v * w.w;
    }
    reinterpret_cast<float4*>(xhat)[(size_t)row * 256 + tid] = acc;
}

// ---------------- streams/events (host objects, created once at init) ----------
namespace {
struct Aux {
    cudaStream_t s1 = nullptr;
    cudaEvent_t  evFork = nullptr;
    cudaEvent_t  evJoin = nullptr;
    Aux() {
        cudaStreamCreateWithFlags(&s1, cudaStreamNonBlocking);
        cudaEventCreateWithFlags(&evFork, cudaEventDisableTiming);
        cudaEventCreateWithFlags(&evJoin, cudaEventDisableTiming);
    }
};
Aux g_aux;
}

// ---------------- launch ------------------------------------------------------
extern "C" void kernel_launch(void* const* d_in, const int* in_sizes, int n_in,
                              void* d_out, int out_size) {
    const float* x    = (const float*)d_in[0];
    const float* Wenc = (const float*)d_in[1];
    const float* benc = (const float*)d_in[2];
    const float* Wdec = (const float*)d_in[3];
    const float* bdec = (const float*)d_in[4];

    float* out  = (float*)d_out;
    float* xhat = out;
    float* hsp  = out + (size_t)BATCH * DDIM;
    float* hpre = hsp + (size_t)BATCH * NDIM;

    cudaFuncSetAttribute(gemm_mma_kernel, cudaFuncAttributeMaxDynamicSharedMemorySize, GEMM_SMEM);
    cudaFuncSetAttribute(topk_kernel,     cudaFuncAttributeMaxDynamicSharedMemorySize, TOPK_SMEM);

    prep_kernel<<<20480, 256>>>(x, bdec, Wenc);

    // fork AFTER prep: transpose overlaps the GEMM (DRAM idle there), not prep
    cudaEventRecord(g_aux.evFork, 0);
    cudaStreamWaitEvent(g_aux.s1, g_aux.evFork, 0);
    transpose_kernel<<<dim3(NDIM / 32, DDIM / 32), dim3(32, 8), 0, g_aux.s1>>>(Wdec);
    cudaEventRecord(g_aux.evJoin, g_aux.s1);

    gemm_mma_kernel<<<4096, 256, GEMM_SMEM>>>(benc, hpre);
    topk_kernel<<<BATCH, TTHREADS, TOPK_SMEM>>>(hpre, hsp);

    // join: decode needs g_wdt
    cudaStreamWaitEvent(0, g_aux.evJoin, 0);
    decode_kernel<<<BATCH, 256>>>(bdec, xhat);
}

// round 17
// speedup vs baseline: 1.1109x; 1.0844x over previous
#include <cuda_runtime.h>
#include <cuda_fp16.h>
#include <cstdint>

#define BATCH 4096
#define DDIM  1024
#define NDIM  16384
#define KSEL  32

// ---------------- scratch ----------------------------------------------------
__device__ __align__(256) unsigned short g_a0[BATCH * DDIM];
__device__ __align__(256) unsigned short g_a1[BATCH * DDIM];
__device__ __align__(256) unsigned short g_b0[NDIM * DDIM];
__device__ __align__(256) unsigned short g_b1[NDIM * DDIM];
__device__ float g_wdt[NDIM * DDIM];
__device__ int   g_idx[BATCH * KSEL];
__device__ float g_val[BATCH * KSEL];

// ---------------- helpers ------------------------------------------------------
__device__ __forceinline__ uint32_t smem_u32(const void* p) {
    uint32_t a;
    asm("{ .reg .u64 t; cvta.to.shared.u64 t, %1; cvt.u32.u64 %0, t; }" : "=r"(a) : "l"(p));
    return a;
}
__device__ __forceinline__ void cp_async16(uint32_t dst, const void* src) {
    asm volatile("cp.async.cg.shared.global [%0], [%1], 16;" :: "r"(dst), "l"(src));
}
#define LDSM_X4(R, addr) \
    asm volatile("ldmatrix.sync.aligned.m8n8.x4.shared.b16 {%0,%1,%2,%3}, [%4];" \
        : "=r"((R)[0]), "=r"((R)[1]), "=r"((R)[2]), "=r"((R)[3]) : "r"(addr))

__device__ __forceinline__ void mma16816(float* c, const uint32_t* a, const uint32_t* b) {
    asm volatile("mma.sync.aligned.m16n8k16.row.col.f32.f16.f16.f32 "
        "{%0,%1,%2,%3}, {%4,%5,%6,%7}, {%8,%9}, {%0,%1,%2,%3};"
        : "+f"(c[0]), "+f"(c[1]), "+f"(c[2]), "+f"(c[3])
        : "r"(a[0]), "r"(a[1]), "r"(a[2]), "r"(a[3]), "r"(b[0]), "r"(b[1]));
}

// ---------------- split conversion (fp16 2-term) ------------------------------
__device__ __forceinline__ void split2(float a, unsigned short& h0, unsigned short& h1) {
    __half b0 = __float2half_rn(a);
    float r = a - __half2float(b0);
    __half b1 = __float2half_rn(r);
    h0 = __half_as_ushort(b0);
    h1 = __half_as_ushort(b1);
}

// ---------------- fused prep: convA + convB + transpose (R13 structure) -------
__global__ __launch_bounds__(256) void prep_kernel(const float* __restrict__ x,
                                                   const float* __restrict__ bdec,
                                                   const float* __restrict__ wenc,
                                                   const float* __restrict__ wdec) {
    const int b = blockIdx.x;
    const int tid = threadIdx.x;
    if (b < 4096) {
        int i = b * 256 + tid;
        float4 xv = reinterpret_cast<const float4*>(x)[i];
        float4 bv = reinterpret_cast<const float4*>(bdec)[i & 255];
        float a[4] = {xv.x - bv.x, xv.y - bv.y, xv.z - bv.z, xv.w - bv.w};
        ushort4 o0, o1;
        split2(a[0], o0.x, o1.x); split2(a[1], o0.y, o1.y);
        split2(a[2], o0.z, o1.z); split2(a[3], o0.w, o1.w);
        reinterpret_cast<ushort4*>(g_a0)[i] = o0;
        reinterpret_cast<ushort4*>(g_a1)[i] = o1;
    } else if (b < 20480) {
        int i = (b - 4096) * 256 + tid;
        float4 xv = reinterpret_cast<const float4*>(wenc)[i];
        float a[4] = {xv.x, xv.y, xv.z, xv.w};
        ushort4 o0, o1;
        split2(a[0], o0.x, o1.x); split2(a[1], o0.y, o1.y);
        split2(a[2], o0.z, o1.z); split2(a[3], o0.w, o1.w);
        reinterpret_cast<ushort4*>(g_b0)[i] = o0;
        reinterpret_cast<ushort4*>(g_b1)[i] = o1;
    } else {
        __shared__ float tile[32][33];
        int idx = b - 20480;
        int bx = idx & 511;
        int by = idx >> 9;
        int tx = tid & 31, ty = tid >> 5;
        int n  = bx * 32 + tx;
        int d0 = by * 32;
#pragma unroll
        for (int i = ty; i < 32; i += 8)
            tile[i][tx] = wdec[(size_t)(d0 + i) * NDIM + n];
        __syncthreads();
        int d  = d0 + tx;
        int n0 = bx * 32;
#pragma unroll
        for (int i = ty; i < 32; i += 8)
            g_wdt[(size_t)(n0 + i) * DDIM + d] = tile[tx][i];
    }
}

// ---------------- mma.sync GEMM: h_pre = (x-b_dec) @ W_enc^T + b_enc ---------
// R7 inner loop (known-good: 872us, tensor 78.3%)
#define TILE_B   (128 * 64)
#define STAGE_B  (4 * TILE_B)
#define GEMM_SMEM (3 * STAGE_B)

__device__ __forceinline__ uint32_t swz(int r, int s) {
    return (uint32_t)(r * 64 + ((s ^ ((r >> 1) & 3)) << 4));
}

__global__ __launch_bounds__(256, 2) void gemm_mma_kernel(const float* __restrict__ benc,
                                                          float* __restrict__ hpre) {
    extern __shared__ unsigned char smem[];
    __shared__ float sbenc[128];
    const uint32_t sb = smem_u32(smem);
    const int tid  = threadIdx.x;
    const int wid  = tid >> 5;
    const int lane = tid & 31;

    const int bid  = blockIdx.x;
    const int band = bid >> 11;
    const int rr   = bid & 2047;
    const int nb   = rr >> 4;
    const int mb   = (band << 4) + (rr & 15);
    const int m0 = mb * 128, n0 = nb * 128;

    if (tid < 128) sbenc[tid] = benc[n0 + tid];

    const unsigned short* srcs[4] = {
        g_a0 + (size_t)m0 * DDIM, g_a1 + (size_t)m0 * DDIM,
        g_b0 + (size_t)n0 * DDIM, g_b1 + (size_t)n0 * DDIM };

    auto load_stage = [&](int kt) {
        const uint32_t base = sb + (uint32_t)(kt % 3) * STAGE_B;
#pragma unroll
        for (int t = 0; t < 4; t++) {
            const unsigned short* src = srcs[t] + kt * 32;
#pragma unroll
            for (int i = 0; i < 2; i++) {
                int id = tid + i * 256;
                int row = id >> 2, seg = id & 3;
                cp_async16(base + (uint32_t)t * TILE_B + swz(row, seg),
                           src + (size_t)row * DDIM + seg * 8);
            }
        }
        asm volatile("cp.async.commit_group;" ::: "memory");
    };

    float c[4][4][4];
#pragma unroll
    for (int i = 0; i < 4; i++)
#pragma unroll
        for (int j = 0; j < 4; j++)
#pragma unroll
            for (int q = 0; q < 4; q++) c[i][j][q] = 0.0f;

    const int wm = wid & 1;
    const int wn = wid >> 1;

    const int a_row = wm * 64 + (lane & 15);
    const int a_hi  = lane >> 4;
    const int b_row = wn * 32 + (lane & 7) + ((lane >> 4) << 3);
    const int b_hi  = (lane >> 3) & 1;

    load_stage(0);
    load_stage(1);

    for (int kt = 0; kt < 32; kt++) {
        if (kt < 31) asm volatile("cp.async.wait_group 1;" ::: "memory");
        else         asm volatile("cp.async.wait_group 0;" ::: "memory");
        __syncthreads();
        if (kt + 2 < 32) load_stage(kt + 2);

        const uint32_t base = sb + (uint32_t)(kt % 3) * STAGE_B;
        const uint32_t aB0 = base, aB1 = base + TILE_B;
        const uint32_t bB0 = base + 2 * TILE_B, bB1 = base + 3 * TILE_B;

#pragma unroll
        for (int kk = 0; kk < 2; kk++) {
            uint32_t b0f[4][2], b1f[4][2];
#pragma unroll
            for (int p = 0; p < 2; p++) {
                uint32_t off = swz(b_row + p * 16, kk * 2 + b_hi);
                uint32_t r4[4];
                LDSM_X4(r4, bB0 + off);
                b0f[2*p][0] = r4[0]; b0f[2*p][1] = r4[1];
                b0f[2*p+1][0] = r4[2]; b0f[2*p+1][1] = r4[3];
                LDSM_X4(r4, bB1 + off);
                b1f[2*p][0] = r4[0]; b1f[2*p][1] = r4[1];
                b1f[2*p+1][0] = r4[2]; b1f[2*p+1][1] = r4[3];
            }
#pragma unroll
            for (int mi = 0; mi < 4; mi++) {
                uint32_t a0f[4], a1f[4];
                uint32_t off = swz(a_row + mi * 16, kk * 2 + a_hi);
                LDSM_X4(a0f, aB0 + off);
                LDSM_X4(a1f, aB1 + off);
#pragma unroll
                for (int ni = 0; ni < 4; ni++) {
                    mma16816(c[mi][ni], a0f, b0f[ni]);
                    mma16816(c[mi][ni], a0f, b1f[ni]);
                    mma16816(c[mi][ni], a1f, b0f[ni]);
                }
            }
        }
    }
    __syncthreads();

    const int erow = m0 + wm * 64 + (lane >> 2);
    const int ecol0 = wn * 32 + (lane & 3) * 2;
#pragma unroll
    for (int mi = 0; mi < 4; mi++) {
#pragma unroll
        for (int ni = 0; ni < 4; ni++) {
            const int col = ecol0 + ni * 8;
            const float be0 = sbenc[col], be1 = sbenc[col + 1];
            float* p0 = hpre + (size_t)(erow + mi * 16) * NDIM + n0 + col;
            float* p1 = hpre + (size_t)(erow + mi * 16 + 8) * NDIM + n0 + col;
            float2 v0 = {c[mi][ni][0] + be0, c[mi][ni][1] + be1};
            float2 v1 = {c[mi][ni][2] + be0, c[mi][ni][3] + be1};
            __stcs(reinterpret_cast<float2*>(p0), v0);
            __stcs(reinterpret_cast<float2*>(p1), v1);
        }
    }
}

// ---------------- top-k: filtered compaction + radix over candidates ----------
#define CAND_MAX 2048
#define EQCAP    256
#define TOPK_SMEM ((NDIM + 256 + 32 + CAND_MAX + EQCAP) * 4)
#define TTHREADS 512
// key_of(3.0f): all top-32 values (~4.1) pass this filter with ~7-sigma margin
#define FILTER_KEY 0xC0400000u

__device__ __forceinline__ void suffix_scan256_w16(unsigned val, volatile unsigned* shm32,
                                                   int tid, unsigned& ge, unsigned& gt) {
    const int lane = tid & 31;
    const int wid  = tid >> 5;
    unsigned v = val;
    if (wid < 8) {
#pragma unroll
        for (int off = 1; off < 32; off <<= 1) {
            unsigned t = __shfl_down_sync(0xFFFFFFFFu, v, off);
            if (lane + off < 32) v += t;
        }
        if (lane == 0) shm32[wid] = v;
    }
    __syncthreads();
    if (wid == 0) {
        unsigned w = (lane < 8) ? shm32[lane] : 0u;
        unsigned u = w;
#pragma unroll
        for (int off = 1; off < 8; off <<= 1) {
            unsigned t = __shfl_down_sync(0xFFFFFFFFu, u, off);
            if (lane + off < 8) u += t;
        }
        if (lane < 8) shm32[16 + lane] = u - w;
    }
    __syncthreads();
    if (wid < 8) {
        unsigned tx = shm32[16 + wid];
        v += tx;
        ge = v;
        unsigned nv = __shfl_down_sync(0xFFFFFFFFu, v, 1);
        gt = (lane < 31) ? nv : tx;
    } else {
        ge = 0; gt = 0;
    }
}

__device__ __forceinline__ unsigned key_xform(unsigned u) {
    return (u & 0x80000000u) ? ~u : (u | 0x80000000u);
}
__device__ __forceinline__ float val_of(unsigned u) {
    return __uint_as_float((u >> 31) ? (u ^ 0x80000000u) : ~u);
}

__global__ __launch_bounds__(TTHREADS, 3) void topk_kernel(const float* __restrict__ hpre,
                                                           float* __restrict__ hsparse) {
    extern __shared__ unsigned sm[];
    unsigned* keys  = sm;                      // 16384
    unsigned* hist  = sm + NDIM;               // 256
    unsigned* shm32 = hist + 256;              // 32
    unsigned* ckey  = shm32 + 32;              // CAND_MAX
    unsigned* eqlst = ckey + CAND_MAX;         // EQCAP
    __shared__ unsigned s_b, s_kr, s_nc, s_ngt, s_neq;
    const int row = blockIdx.x;
    const int tid = threadIdx.x;
    const int lane = tid & 31;
    const float* in = hpre + (size_t)row * NDIM;
    const uint32_t keys_sm = smem_u32(keys);

    // stage whole row via cp.async
#pragma unroll
    for (int i = 0; i < 8; i++) {
        int c = tid + i * TTHREADS;
        cp_async16(keys_sm + (uint32_t)c * 16u, in + c * 4);
    }
    asm volatile("cp.async.commit_group;" ::: "memory");
    if (tid == 0) { s_nc = 0; s_ngt = 0; s_neq = 0; }
    asm volatile("cp.async.wait_group 0;" ::: "memory");
    __syncthreads();

    // single merged sweep: transform in place + filtered ballot compaction
    for (int i = tid; i < NDIM / 4; i += TTHREADS) {
        uint4 r = reinterpret_cast<uint4*>(keys)[i];
        unsigned us[4];
        us[0] = key_xform(r.x); us[1] = key_xform(r.y);
        us[2] = key_xform(r.z); us[3] = key_xform(r.w);
        uint4 o = {us[0], us[1], us[2], us[3]};
        reinterpret_cast<uint4*>(keys)[i] = o;
#pragma unroll
        for (int c = 0; c < 4; c++) {
            bool p = us[c] > FILTER_KEY;
            unsigned ball = __ballot_sync(0xFFFFFFFFu, p);
            if (ball) {
                unsigned base = 0;
                if (lane == 0) base = atomicAdd(&s_nc, (unsigned)__popc(ball));
                base = __shfl_sync(0xFFFFFFFFu, base, 0);
                if (p) {
                    unsigned pos = base + __popc(ball & ((1u << lane) - 1u));
                    if (pos < CAND_MAX) ckey[pos] = us[c];
                }
            }
        }
    }
    __syncthreads();
    const unsigned ncand = s_nc;
    const bool fallback = (ncand < KSEL) || (ncand > (unsigned)CAND_MAX);
    const unsigned* csrc = fallback ? keys : ckey;
    const unsigned nc = fallback ? (unsigned)NDIM : ncand;

    // full radix select (4 passes) over candidates (or all keys on fallback)
    unsigned prefix = 0, pmask = 0, krem = KSEL;
    for (int shift = 24; shift >= 0; shift -= 8) {
        if (tid < 256) hist[tid] = 0;
        __syncthreads();
        for (unsigned j = tid; j < nc; j += TTHREADS) {
            unsigned u = csrc[j];
            if ((u & pmask) == prefix) atomicAdd(&hist[(u >> shift) & 255], 1u);
        }
        __syncthreads();
        unsigned ge, gt;
        unsigned hv = (tid < 256) ? hist[tid] : 0u;
        suffix_scan256_w16(hv, shm32, tid, ge, gt);
        if (tid < 256 && gt < krem && krem <= ge) { s_b = (unsigned)tid; s_kr = krem - gt; }
        __syncthreads();
        prefix |= (s_b << shift);
        pmask  |= (0xFFu << shift);
        krem = s_kr;
        __syncthreads();
    }
    const unsigned T = prefix;
    const unsigned needeq = krem;

    // output sweep: vectorized, write h_sparse (streaming) + collect winners
    float* outrow = hsparse + (size_t)row * NDIM;
    for (int i = tid; i < NDIM / 4; i += TTHREADS) {
        uint4 r = reinterpret_cast<uint4*>(keys)[i];
        unsigned us[4] = {r.x, r.y, r.z, r.w};
        float4 f;
        f.x = (us[0] > T) ? val_of(us[0]) : 0.0f;
        f.y = (us[1] > T) ? val_of(us[1]) : 0.0f;
        f.z = (us[2] > T) ? val_of(us[2]) : 0.0f;
        f.w = (us[3] > T) ? val_of(us[3]) : 0.0f;
        __stcs(reinterpret_cast<float4*>(outrow) + i, f);
#pragma unroll
        for (int c = 0; c < 4; c++) {
            if (us[c] > T) {
                unsigned slot = atomicAdd(&s_ngt, 1u);
                g_idx[row * KSEL + slot] = 4 * i + c;
                g_val[row * KSEL + slot] = val_of(us[c]);
            } else if (us[c] == T) {
                unsigned p = atomicAdd(&s_neq, 1u);
                if (p < EQCAP) eqlst[p] = (unsigned)(4 * i + c);
            }
        }
    }
    __syncthreads();

    // resolve ties deterministically: first `needeq` ==T elements by index
    if (tid == 0) {
        const float tv = val_of(T);
        unsigned base = s_ngt;
        unsigned ne = s_neq;
        if (ne <= EQCAP) {
            for (unsigned a = 1; a < ne; a++) {
                unsigned v = eqlst[a]; int b = (int)a - 1;
                while (b >= 0 && eqlst[b] > v) { eqlst[b+1] = eqlst[b]; b--; }
                eqlst[b+1] = v;
            }
            for (unsigned t = 0; t < needeq; t++) {
                unsigned idx = eqlst[t];
                g_idx[row * KSEL + base + t] = (int)idx;
                g_val[row * KSEL + base + t] = tv;
                outrow[idx] = tv;
            }
        } else {
            unsigned got = 0;
            for (int i = 0; i < NDIM && got < needeq; i++) {
                if (keys[i] == T) {
                    g_idx[row * KSEL + base + got] = i;
                    g_val[row * KSEL + base + got] = tv;
                    outrow[i] = tv;
                    got++;
                }
            }
        }
    }
}

// ---------------- sparse decode (separate kernel) -------------------------------
__global__ __launch_bounds__(256) void decode_kernel(const float* __restrict__ bdec,
                                                     float* __restrict__ xhat) {
    __shared__ int   sidx[KSEL];
    __shared__ float sval[KSEL];
    const int row = blockIdx.x;
    const int tid = threadIdx.x;
    if (tid < KSEL) {
        int   idx = g_idx[row * KSEL + tid];
        float v   = g_val[row * KSEL + tid];
        int rank = 0;
#pragma unroll
        for (int j = 0; j < KSEL; j++) {
            int oj = __shfl_sync(0xFFFFFFFFu, idx, j);
            rank += (oj < idx);
        }
        sidx[rank] = idx;
        sval[rank] = v;
    }
    __syncthreads();
    float4 acc = reinterpret_cast<const float4*>(bdec)[tid];
#pragma unroll
    for (int j = 0; j < KSEL; j++) {
        float v = sval[j];
        float4 w = reinterpret_cast<const float4*>(g_wdt + (size_t)sidx[j] * DDIM)[tid];
        acc.x += v * w.x; acc.y += v * w.y; acc.z += v * w.z; acc.w += v * w.w;
    }
    reinterpret_cast<float4*>(xhat)[(size_t)row * 256 + tid] = acc;
}

// ---------------- launch ------------------------------------------------------
extern "C" void kernel_launch(void* const* d_in, const int* in_sizes, int n_in,
                              void* d_out, int out_size) {
    const float* x    = (const float*)d_in[0];
    const float* Wenc = (const float*)d_in[1];
    const float* benc = (const float*)d_in[2];
    const float* Wdec = (const float*)d_in[3];
    const float* bdec = (const float*)d_in[4];

    float* out  = (float*)d_out;
    float* xhat = out;
    float* hsp  = out + (size_t)BATCH * DDIM;
    float* hpre = hsp + (size_t)BATCH * NDIM;

    cudaFuncSetAttribute(gemm_mma_kernel, cudaFuncAttributeMaxDynamicSharedMemorySize, GEMM_SMEM);
    cudaFuncSetAttribute(topk_kernel,     cudaFuncAttributeMaxDynamicSharedMemorySize, TOPK_SMEM);

    prep_kernel<<<36864, 256>>>(x, bdec, Wenc, Wdec);
    gemm_mma_kernel<<<4096, 256, GEMM_SMEM>>>(benc, hpre);
    topk_kernel<<<BATCH, TTHREADS, TOPK_SMEM>>>(hpre, hsp);
    decode_kernel<<<BATCH, 256>>>(bdec, xhat);
}